// round 6
// baseline (speedup 1.0000x reference)
#include <cuda_runtime.h>

// ---------------------------------------------------------------------------
// RGCN gather-MM:  out[dst[e]] += feat[src[e]] @ W[etype[e]]
//   E = 1,000,000 edges, N = 100,000 nodes, D_in = D_out = 64, R = 16
//
// Pipeline (all graph-capturable, no allocations):
//   1. k_zero     : zero d_out (poisoned by harness)
//   2. k_hist     : per-block relation histograms
//   3. k_scan     : column-wise exclusive scan -> per-(block,rel) bases,
//                   relation offsets, and the tile table for the main kernel
//   4. k_scatter  : counting-sort (src,dst) by relation into static scratch
//   5. k_rgcn     : per-relation grouped GEMM, W in smem (broadcast loads),
//                   gathered h tiles in smem, fma.rn.f32x2 accumulation,
//                   red.global.add.v4.f32 scatter to out
// ---------------------------------------------------------------------------

#define E_MAX    1000000
#define NB_SORT  1024
#define TILE     256
#define BLK      128
#define MAXT     3922   // sum_r ceil(cnt_r/TILE) <= ceil(E/TILE) + 15 = 3922

// scratch (static device arrays; allocation is forbidden)
__device__ int g_src_s[E_MAX];
__device__ int g_dst_s[E_MAX];
__device__ int g_blockcounts[NB_SORT * 16];   // reused as per-block bases after scan
__device__ int g_relofs[17];
__device__ int g_tile_rel[MAXT];
__device__ int g_tile_base[MAXT];

// ---------------------------------------------------------------------------
__global__ void k_zero(float4* out, int n4) {
    int i = blockIdx.x * blockDim.x + threadIdx.x;
    if (i < n4) out[i] = make_float4(0.f, 0.f, 0.f, 0.f);
}

// ---------------------------------------------------------------------------
__global__ void k_hist(const int* __restrict__ et, int E, int chunk) {
    __shared__ int cnt[16];
    if (threadIdx.x < 16) cnt[threadIdx.x] = 0;
    __syncthreads();
    int lo = blockIdx.x * chunk;
    int hi = min(E, lo + chunk);
    for (int e = lo + threadIdx.x; e < hi; e += blockDim.x)
        atomicAdd(&cnt[et[e]], 1);
    __syncthreads();
    if (threadIdx.x < 16)
        g_blockcounts[blockIdx.x * 16 + threadIdx.x] = cnt[threadIdx.x];
}

// ---------------------------------------------------------------------------
// single block, 512 threads: warp r scans column r over all sort blocks.
__global__ void k_scan(int nb) {
    __shared__ int rel_total[16];
    __shared__ int relofs_s[17];
    __shared__ int tileofs_s[17];
    int w = threadIdx.x >> 5, lane = threadIdx.x & 31;
    if (w < 16) {
        int carry = 0;
        for (int c = 0; c < nb; c += 32) {
            int b = c + lane;
            int v = (b < nb) ? g_blockcounts[b * 16 + w] : 0;
            int s = v;
            #pragma unroll
            for (int d = 1; d < 32; d <<= 1) {
                int t = __shfl_up_sync(0xffffffffu, s, d);
                if (lane >= d) s += t;
            }
            if (b < nb) g_blockcounts[b * 16 + w] = carry + s - v;  // exclusive base
            carry += __shfl_sync(0xffffffffu, s, 31);
        }
        if (lane == 0) rel_total[w] = carry;
    }
    __syncthreads();
    if (threadIdx.x == 0) {
        int acc = 0, tacc = 0;
        for (int r = 0; r < 16; r++) {
            relofs_s[r] = acc; tileofs_s[r] = tacc; g_relofs[r] = acc;
            acc  += rel_total[r];
            tacc += (rel_total[r] + TILE - 1) / TILE;
        }
        relofs_s[16] = acc; tileofs_s[16] = tacc; g_relofs[16] = acc;
    }
    __syncthreads();
    int ntiles = tileofs_s[16];
    for (int t = threadIdx.x; t < MAXT; t += blockDim.x) {
        if (t < ntiles) {
            int r = 0;
            while (t >= tileofs_s[r + 1]) r++;
            g_tile_rel[t]  = r;
            g_tile_base[t] = relofs_s[r] + (t - tileofs_s[r]) * TILE;
        } else {
            g_tile_rel[t] = -1;
        }
    }
}

// ---------------------------------------------------------------------------
__global__ void k_scatter(const int* __restrict__ src, const int* __restrict__ dst,
                          const int* __restrict__ et, int E, int chunk) {
    __shared__ int cur[16];
    if (threadIdx.x < 16)
        cur[threadIdx.x] = g_relofs[threadIdx.x] +
                           g_blockcounts[blockIdx.x * 16 + threadIdx.x];
    __syncthreads();
    int lo = blockIdx.x * chunk, hi = min(E, lo + chunk);
    for (int e = lo + threadIdx.x; e < hi; e += blockDim.x) {
        int r = et[e];
        int pos = atomicAdd(&cur[r], 1);
        g_src_s[pos] = src[e];
        g_dst_s[pos] = dst[e];
    }
}

// ---------------------------------------------------------------------------
// packed fp32x2 FMA: acc{lo,hi} += a{lo,hi} * b{lo,hi}
#define FMA2(acc, a, b) \
    asm("fma.rn.f32x2 %0, %1, %2, %0;" : "+l"(acc) : "l"(a), "l"(b))

// smem layout: W[64*64] floats | h[256*68] floats | src[256] int | dst[256] int
#define SMEM_BYTES ((4096 + TILE * 68) * 4 + TILE * 8)

__global__ __launch_bounds__(BLK) void k_rgcn(const float* __restrict__ feat,
                                              const float* __restrict__ Wt,
                                              float* __restrict__ out) {
    extern __shared__ float sm[];
    float* Wsm = sm;                       // 4096 floats (16 KB)
    float* hsm = sm + 4096;                // 256 x 68 floats (stride keeps STS.128 aligned)
    int*   srcsh = (int*)(hsm + TILE * 68);
    int*   dsh   = srcsh + TILE;

    int tid = threadIdx.x;
    int rel = g_tile_rel[blockIdx.x];
    if (rel < 0) return;
    int base = g_tile_base[blockIdx.x];
    int n = min(TILE, g_relofs[rel + 1] - base);

    // stage W[rel] (16 KB) into smem, fully coalesced
    {
        const float4* wg  = (const float4*)(Wt + rel * 4096);
        float4*       ws4 = (float4*)Wsm;
        #pragma unroll
        for (int p = 0; p < 8; p++) ws4[tid + p * BLK] = wg[tid + p * BLK];
    }
    // stage src/dst indices for this tile
    #pragma unroll
    for (int p = tid; p < TILE; p += BLK) {
        int ok = p < n;
        srcsh[p] = ok ? g_src_s[base + p] : -1;
        dsh[p]   = ok ? g_dst_s[base + p] : -1;
    }
    __syncthreads();

    // gather h = feat[src] into smem (pairs of 256B rows per warp -> coalesced)
    {
        const float4* featv = (const float4*)feat;
        #pragma unroll
        for (int it = 0; it < (TILE * 16) / BLK; it++) {
            int p = tid + it * BLK;
            int slot = p >> 4, f = p & 15;
            int s = srcsh[slot];
            float4 v = (s >= 0) ? featv[s * 16 + f] : make_float4(0.f, 0.f, 0.f, 0.f);
            *(float4*)&hsm[slot * 68 + f * 4] = v;
        }
    }
    __syncthreads();

    // compute: 2 edges/thread, 64 output cols as 32 packed-f32x2 accumulators each
    const float* h0 = hsm + tid * 68;
    const float* h1 = hsm + (tid + BLK) * 68;
    unsigned long long a0[32], a1[32];
    #pragma unroll
    for (int j = 0; j < 32; j++) { a0[j] = 0ull; a1[j] = 0ull; }

    const ulonglong2* wp = (const ulonglong2*)Wsm;   // row k: 16 x ulonglong2
    #pragma unroll 2
    for (int k = 0; k < 64; k++) {
        unsigned u0 = __float_as_uint(h0[k]);
        unsigned u1 = __float_as_uint(h1[k]);
        unsigned long long p0, p1;
        asm("mov.b64 %0, {%1, %1};" : "=l"(p0) : "r"(u0));
        asm("mov.b64 %0, {%1, %1};" : "=l"(p1) : "r"(u1));
        const ulonglong2* row = wp + k * 16;
        #pragma unroll
        for (int q = 0; q < 16; q++) {
            ulonglong2 wv = row[q];              // smem broadcast (all lanes same rel)
            FMA2(a0[2 * q],     p0, wv.x);
            FMA2(a0[2 * q + 1], p0, wv.y);
            FMA2(a1[2 * q],     p1, wv.x);
            FMA2(a1[2 * q + 1], p1, wv.y);
        }
    }

    // scatter-add with 16B vector reductions
    if (tid < n) {
        float* op = out + (long long)dsh[tid] * 64;
        #pragma unroll
        for (int q = 0; q < 16; q++) {
            unsigned x0, x1, x2, x3;
            asm("mov.b64 {%0, %1}, %2;" : "=r"(x0), "=r"(x1) : "l"(a0[2 * q]));
            asm("mov.b64 {%0, %1}, %2;" : "=r"(x2), "=r"(x3) : "l"(a0[2 * q + 1]));
            asm volatile("red.global.add.v4.f32 [%0], {%1, %2, %3, %4};"
                         :: "l"(op + q * 4),
                            "r"(x0), "r"(x1), "r"(x2), "r"(x3) : "memory");
        }
    }
    if (tid + BLK < n) {
        float* op = out + (long long)dsh[tid + BLK] * 64;
        #pragma unroll
        for (int q = 0; q < 16; q++) {
            unsigned x0, x1, x2, x3;
            asm("mov.b64 {%0, %1}, %2;" : "=r"(x0), "=r"(x1) : "l"(a1[2 * q]));
            asm("mov.b64 {%0, %1}, %2;" : "=r"(x2), "=r"(x3) : "l"(a1[2 * q + 1]));
            asm volatile("red.global.add.v4.f32 [%0], {%1, %2, %3, %4};"
                         :: "l"(op + q * 4),
                            "r"(x0), "r"(x1), "r"(x2), "r"(x3) : "memory");
        }
    }
}

// ---------------------------------------------------------------------------
extern "C" void kernel_launch(void* const* d_in, const int* in_sizes, int n_in,
                              void* d_out, int out_size) {
    const float* feat   = (const float*)d_in[0];   // [N, 64]
    const float* weight = (const float*)d_in[1];   // [16, 64, 64]
    const int*   src    = (const int*)d_in[2];     // [E]
    const int*   dst    = (const int*)d_in[3];     // [E]
    const int*   etyp   = (const int*)d_in[4];     // [E]
    float*       out    = (float*)d_out;           // [N, 64]

    int E = in_sizes[2];
    int n4 = out_size >> 2;

    cudaFuncSetAttribute(k_rgcn, cudaFuncAttributeMaxDynamicSharedMemorySize,
                         SMEM_BYTES);

    k_zero<<<(n4 + 255) / 256, 256>>>((float4*)out, n4);

    int chunk = (E + NB_SORT - 1) / NB_SORT;
    k_hist<<<NB_SORT, 256>>>(etyp, E, chunk);
    k_scan<<<1, 512>>>(NB_SORT);
    k_scatter<<<NB_SORT, 256>>>(src, dst, etyp, E, chunk);

    k_rgcn<<<MAXT, BLK, SMEM_BYTES>>>(feat, weight, out);
}

// round 8
// speedup vs baseline: 1.4210x; 1.4210x over previous
#include <cuda_runtime.h>
#include <cuda_bf16.h>
#include <cstdint>

// ---------------------------------------------------------------------------
// RGCN gather-MM:  out[dst[e]] += feat[src[e]] @ W[etype[e]]
//   E = 1,000,000 edges, N = 100,000 nodes, D_in = D_out = 64, R = 16
//
// Pipeline (portable sm_103 path — no tcgen05; mma.sync bf16 HMMA):
//   1. k_zero   : zero d_out
//   2. k_wprep  : W[r] -> W^T [n][k], bf16 hi/lo split (linear layout)
//   3. k_hist/k_scan/k_scatter : counting-sort edges by relation
//   4. k_rgcn_mma : persistent grouped GEMM, 128-edge tiles, 4 warps/CTA.
//        A[128,64] = gathered feat rows, bf16 hi/lo in padded smem
//        B[64,64]  = W[rel]^T hi/lo in padded smem
//        D = Ah*Bh + Al*Bh + Ah*Bl  (fp32 accum, m16n8k16 mma.sync)
//        epilogue: stage D in smem, red.global.add.v4.f32 scatter
// ---------------------------------------------------------------------------

#define E_MAX    1000000
#define NB_SORT  1024
#define TILE     128
#define BLK      128
#define MAXT     7828       // ceil(E/128) + 15
#define GRID_MMA 608        // 4 CTAs x 152 SMs, persistent

// ---- static device scratch (allocation is forbidden) ----
__device__ int g_src_s[E_MAX];
__device__ int g_dst_s[E_MAX];
__device__ int g_blockcounts[NB_SORT * 16];
__device__ int g_relofs[17];
__device__ int g_tile_rel[MAXT];
__device__ int g_tile_base[MAXT];
__device__ unsigned short g_Bhi[16 * 4096];   // bf16 W^T hi, [r][n][k]
__device__ unsigned short g_Blo[16 * 4096];   // bf16 W^T lo

// ---------------------------------------------------------------------------
__global__ void k_zero(float4* out, int n4) {
    int i = blockIdx.x * blockDim.x + threadIdx.x;
    if (i < n4) out[i] = make_float4(0.f, 0.f, 0.f, 0.f);
}

// ---------------------------------------------------------------------------
// W[r] is [k][n] row-major fp32 -> store B[n][k] bf16 hi/lo, linear.
__global__ void k_wprep(const float* __restrict__ W) {
    int r = blockIdx.x;
    for (int idx = threadIdx.x; idx < 4096; idx += blockDim.x) {
        int n = idx >> 6, k = idx & 63;
        float w = W[r * 4096 + k * 64 + n];
        __nv_bfloat16 h = __float2bfloat16(w);
        __nv_bfloat16 l = __float2bfloat16(w - __bfloat162float(h));
        g_Bhi[r * 4096 + idx] = __bfloat16_as_ushort(h);
        g_Blo[r * 4096 + idx] = __bfloat16_as_ushort(l);
    }
}

// ---------------------------------------------------------------------------
__global__ void k_hist(const int* __restrict__ et, int E, int chunk) {
    __shared__ int cnt[16];
    if (threadIdx.x < 16) cnt[threadIdx.x] = 0;
    __syncthreads();
    int lo = blockIdx.x * chunk;
    int hi = min(E, lo + chunk);
    for (int e = lo + threadIdx.x; e < hi; e += blockDim.x)
        atomicAdd(&cnt[et[e]], 1);
    __syncthreads();
    if (threadIdx.x < 16)
        g_blockcounts[blockIdx.x * 16 + threadIdx.x] = cnt[threadIdx.x];
}

// ---------------------------------------------------------------------------
__global__ void k_scan(int nb) {
    __shared__ int rel_total[16];
    __shared__ int relofs_s[17];
    __shared__ int tileofs_s[17];
    int w = threadIdx.x >> 5, lane = threadIdx.x & 31;
    if (w < 16) {
        int carry = 0;
        for (int c = 0; c < nb; c += 32) {
            int b = c + lane;
            int v = (b < nb) ? g_blockcounts[b * 16 + w] : 0;
            int s = v;
            #pragma unroll
            for (int d = 1; d < 32; d <<= 1) {
                int t = __shfl_up_sync(0xffffffffu, s, d);
                if (lane >= d) s += t;
            }
            if (b < nb) g_blockcounts[b * 16 + w] = carry + s - v;
            carry += __shfl_sync(0xffffffffu, s, 31);
        }
        if (lane == 0) rel_total[w] = carry;
    }
    __syncthreads();
    if (threadIdx.x == 0) {
        int acc = 0, tacc = 0;
        for (int r = 0; r < 16; r++) {
            relofs_s[r] = acc; tileofs_s[r] = tacc; g_relofs[r] = acc;
            acc  += rel_total[r];
            tacc += (rel_total[r] + TILE - 1) / TILE;
        }
        relofs_s[16] = acc; tileofs_s[16] = tacc; g_relofs[16] = acc;
    }
    __syncthreads();
    int ntiles = tileofs_s[16];
    for (int t = threadIdx.x; t < MAXT; t += blockDim.x) {
        if (t < ntiles) {
            int r = 0;
            while (t >= tileofs_s[r + 1]) r++;
            g_tile_rel[t]  = r;
            g_tile_base[t] = relofs_s[r] + (t - tileofs_s[r]) * TILE;
        } else {
            g_tile_rel[t] = -1;
        }
    }
}

// ---------------------------------------------------------------------------
__global__ void k_scatter(const int* __restrict__ src, const int* __restrict__ dst,
                          const int* __restrict__ et, int E, int chunk) {
    __shared__ int cur[16];
    if (threadIdx.x < 16)
        cur[threadIdx.x] = g_relofs[threadIdx.x] +
                           g_blockcounts[blockIdx.x * 16 + threadIdx.x];
    __syncthreads();
    int lo = blockIdx.x * chunk, hi = min(E, lo + chunk);
    for (int e = lo + threadIdx.x; e < hi; e += blockDim.x) {
        int r = et[e];
        int pos = atomicAdd(&cur[r], 1);
        g_src_s[pos] = src[e];
        g_dst_s[pos] = dst[e];
    }
}

// ---------------------------------------------------------------------------
// bf16 m16n8k16 HMMA (sm_80+ portable)
#define MMA_BF16(d, a, b)                                                     \
    asm volatile(                                                             \
        "mma.sync.aligned.m16n8k16.row.col.f32.bf16.bf16.f32 "                \
        "{%0,%1,%2,%3}, {%4,%5,%6,%7}, {%8,%9}, {%0,%1,%2,%3};"               \
        : "+f"((d)[0]), "+f"((d)[1]), "+f"((d)[2]), "+f"((d)[3])              \
        : "r"((a)[0]), "r"((a)[1]), "r"((a)[2]), "r"((a)[3]),                 \
          "r"((b)[0]), "r"((b)[1]))

// smem layout (halves, padded stride 72 to kill bank conflicts)
// A_hi: 128x72 halves (18432 B)   A_lo: 18432 B
// B_hi:  64x72 halves ( 9216 B)   B_lo:  9216 B
// src/dst: 512 B each
#define SM_AHI  0
#define SM_ALO  18432
#define SM_BHI  36864
#define SM_BLO  46080
#define SM_SRC  55296
#define SM_DST  55808
#define SMEM_DYN 56320
#define ASTRIDE 72   // halves per row

__global__ __launch_bounds__(BLK, 4) void k_rgcn_mma(const float* __restrict__ feat,
                                                     float* __restrict__ out) {
    extern __shared__ char smb[];
    unsigned short* Ah = (unsigned short*)(smb + SM_AHI);
    unsigned short* Al = (unsigned short*)(smb + SM_ALO);
    unsigned short* Bh = (unsigned short*)(smb + SM_BHI);
    unsigned short* Bl = (unsigned short*)(smb + SM_BLO);
    int* srcsh = (int*)(smb + SM_SRC);
    int* dsh   = (int*)(smb + SM_DST);
    float* Dst = (float*)smb;            // epilogue staging overlays A (128x68 f32)

    int tid = threadIdx.x, w = tid >> 5, lane = tid & 31;
    int g = lane >> 2, tig = lane & 3;   // mma quad indexing

    const float4* featv = (const float4*)feat;

    for (int t = blockIdx.x; t < MAXT; t += gridDim.x) {
        int rel = g_tile_rel[t];
        if (rel < 0) break;
        int base = g_tile_base[t];
        int n = min(TILE, g_relofs[rel + 1] - base);

        // stage indices
        {
            int ok = tid < n;
            srcsh[tid] = ok ? g_src_s[base + tid] : -1;
            dsh[tid]   = ok ? g_dst_s[base + tid] : -1;
        }
        // copy B hi/lo into padded smem (8 halves per uint4, row-aligned)
        #pragma unroll
        for (int c = 0; c < 4; c++) {
            int p8  = tid + c * BLK;          // 512 uint4 chunks total
            int idx = p8 * 8;                 // half index in [n][k] linear
            int nr = idx >> 6, k = idx & 63;
            *(uint4*)(Bh + nr * ASTRIDE + k) =
                *(const uint4*)(g_Bhi + rel * 4096 + idx);
            *(uint4*)(Bl + nr * ASTRIDE + k) =
                *(const uint4*)(g_Blo + rel * 4096 + idx);
        }
        __syncthreads();

        // gather + split-convert A: 16 lanes cooperate on one 256B feat row
        #pragma unroll
        for (int it = 0; it < 16; it++) {
            int p = tid + it * BLK;
            int row = p >> 4, f = p & 15;
            int s = srcsh[row];
            float4 v = (s >= 0) ? featv[(long long)s * 16 + f]
                                : make_float4(0.f, 0.f, 0.f, 0.f);
            __nv_bfloat16 bx = __float2bfloat16(v.x);
            __nv_bfloat16 by = __float2bfloat16(v.y);
            __nv_bfloat16 bz = __float2bfloat16(v.z);
            __nv_bfloat16 bw = __float2bfloat16(v.w);
            __nv_bfloat16 lx = __float2bfloat16(v.x - __bfloat162float(bx));
            __nv_bfloat16 ly = __float2bfloat16(v.y - __bfloat162float(by));
            __nv_bfloat16 lz = __float2bfloat16(v.z - __bfloat162float(bz));
            __nv_bfloat16 lw = __float2bfloat16(v.w - __bfloat162float(bw));
            unsigned h01 = (unsigned)__bfloat16_as_ushort(bx) |
                           ((unsigned)__bfloat16_as_ushort(by) << 16);
            unsigned h23 = (unsigned)__bfloat16_as_ushort(bz) |
                           ((unsigned)__bfloat16_as_ushort(bw) << 16);
            unsigned l01 = (unsigned)__bfloat16_as_ushort(lx) |
                           ((unsigned)__bfloat16_as_ushort(ly) << 16);
            unsigned l23 = (unsigned)__bfloat16_as_ushort(lz) |
                           ((unsigned)__bfloat16_as_ushort(lw) << 16);
            *(uint2*)(Ah + row * ASTRIDE + f * 4) = make_uint2(h01, h23);
            *(uint2*)(Al + row * ASTRIDE + f * 4) = make_uint2(l01, l23);
        }
        __syncthreads();

        // ---- GEMM: warp w owns rows [32w, 32w+32) = 2 m16 blocks x 8 n8 blocks
        float acc[2][8][4];
        #pragma unroll
        for (int m = 0; m < 2; m++)
            #pragma unroll
            for (int nb = 0; nb < 8; nb++)
                #pragma unroll
                for (int j = 0; j < 4; j++) acc[m][nb][j] = 0.f;

        #pragma unroll
        for (int ks = 0; ks < 4; ks++) {
            int kc = ks * 16 + 2 * tig;   // k column of this thread's A/B pair
            unsigned ah[2][4], al[2][4];
            #pragma unroll
            for (int m = 0; m < 2; m++) {
                int r0 = (32 * w + 16 * m + g) * ASTRIDE + kc;
                int r1 = r0 + 8 * ASTRIDE;
                ah[m][0] = *(const unsigned*)(Ah + r0);
                ah[m][1] = *(const unsigned*)(Ah + r1);
                ah[m][2] = *(const unsigned*)(Ah + r0 + 8);
                ah[m][3] = *(const unsigned*)(Ah + r1 + 8);
                al[m][0] = *(const unsigned*)(Al + r0);
                al[m][1] = *(const unsigned*)(Al + r1);
                al[m][2] = *(const unsigned*)(Al + r0 + 8);
                al[m][3] = *(const unsigned*)(Al + r1 + 8);
            }
            #pragma unroll
            for (int nb = 0; nb < 8; nb++) {
                int b0 = (8 * nb + g) * ASTRIDE + kc;
                unsigned bh[2], bl[2];
                bh[0] = *(const unsigned*)(Bh + b0);
                bh[1] = *(const unsigned*)(Bh + b0 + 8);
                bl[0] = *(const unsigned*)(Bl + b0);
                bl[1] = *(const unsigned*)(Bl + b0 + 8);
                #pragma unroll
                for (int m = 0; m < 2; m++) {
                    MMA_BF16(acc[m][nb], ah[m], bh);
                    MMA_BF16(acc[m][nb], al[m], bh);
                    MMA_BF16(acc[m][nb], ah[m], bl);
                }
            }
        }
        __syncthreads();   // done reading A/B smem; reuse as D staging

        // stage D: c0,c1 -> row g, cols 8nb+2tig..; c2,c3 -> row g+8
        #pragma unroll
        for (int m = 0; m < 2; m++) {
            int r0 = 32 * w + 16 * m + g;
            #pragma unroll
            for (int nb = 0; nb < 8; nb++) {
                int c = 8 * nb + 2 * tig;
                *(float2*)(Dst + r0 * 68 + c) =
                    make_float2(acc[m][nb][0], acc[m][nb][1]);
                *(float2*)(Dst + (r0 + 8) * 68 + c) =
                    make_float2(acc[m][nb][2], acc[m][nb][3]);
            }
        }
        __syncthreads();

        // scatter: thread tid handles row tid, 16 x red.v4
        if (tid < n) {
            float* op = out + (long long)dsh[tid] * 64;
            const float4* dr = (const float4*)(Dst + tid * 68);
            #pragma unroll
            for (int q = 0; q < 16; q++) {
                float4 v = dr[q];
                asm volatile("red.global.add.v4.f32 [%0], {%1, %2, %3, %4};"
                             :: "l"(op + q * 4),
                                "f"(v.x), "f"(v.y), "f"(v.z), "f"(v.w)
                             : "memory");
            }
        }
        __syncthreads();   // staging area reused as A next iteration
    }
}

// ---------------------------------------------------------------------------
extern "C" void kernel_launch(void* const* d_in, const int* in_sizes, int n_in,
                              void* d_out, int out_size) {
    const float* feat   = (const float*)d_in[0];   // [N, 64]
    const float* weight = (const float*)d_in[1];   // [16, 64, 64]
    const int*   src    = (const int*)d_in[2];     // [E]
    const int*   dst    = (const int*)d_in[3];     // [E]
    const int*   etyp   = (const int*)d_in[4];     // [E]
    float*       out    = (float*)d_out;           // [N, 64]

    int E = in_sizes[2];
    int n4 = out_size >> 2;

    cudaFuncSetAttribute(k_rgcn_mma, cudaFuncAttributeMaxDynamicSharedMemorySize,
                         SMEM_DYN);

    k_zero<<<(n4 + 255) / 256, 256>>>((float4*)out, n4);
    k_wprep<<<16, 256>>>(weight);

    int chunk = (E + NB_SORT - 1) / NB_SORT;
    k_hist<<<NB_SORT, 256>>>(etyp, E, chunk);
    k_scan<<<1, 512>>>(NB_SORT);
    k_scatter<<<NB_SORT, 256>>>(src, dst, etyp, E, chunk);

    k_rgcn_mma<<<GRID_MMA, BLK, SMEM_DYN>>>(feat, out);
}

// round 10
// speedup vs baseline: 1.5769x; 1.1097x over previous
#include <cuda_runtime.h>
#include <cuda_fp16.h>
#include <cstdint>

// ---------------------------------------------------------------------------
// RGCN gather-MM:  out[dst[e]] += feat[src[e]] @ W[etype[e]]
//   E = 1,000,000 edges, N = 100,000 nodes, D_in = D_out = 64, R = 16
//
// Pipeline (4 launches):
//   1. k_prep    : fused  zero(out) + W^T fp16 prep + per-block rel histogram
//   2. k_scan    : parallel column scan -> bases, rel offsets, tile table
//   3. k_scatter : counting-sort (src,dst) by relation
//   4. k_rgcn_mma: persistent grouped GEMM, 128-edge tiles, 4 warps/CTA.
//        A[128,64] gathered feat rows, fp16 hi/lo split in padded smem
//        B[64,64]  = W[rel]^T fp16 (hi only), reloaded only on rel change
//        D = Ah*Bh + Al*Bh (fp32 accum, m16n8k16 mma.sync fp16)
//        epilogue: stage D in smem (overlays A), red.global.add.v4.f32
// ---------------------------------------------------------------------------

#define E_MAX    1000000
#define NB_SORT  1024
#define TILE     128
#define BLK      128
#define MAXT     7828       // ceil(E/128) + 15
#define GRID_MMA 608        // 4 CTAs x 152 SMs

// ---- static device scratch (allocation is forbidden) ----
__device__ int g_src_s[E_MAX];
__device__ int g_dst_s[E_MAX];
__device__ int g_blockcounts[NB_SORT * 16];
__device__ int g_relofs[17];
__device__ int g_tile_rel[MAXT];
__device__ int g_tile_base[MAXT];
__device__ unsigned short g_Bh[16 * 4096];   // fp16 W^T, [r][n][k]

// ---------------------------------------------------------------------------
// fused: zero out + prep W + per-block relation histogram
__global__ void k_prep(float4* out, int n4, const float* __restrict__ W,
                       const int* __restrict__ et, int E, int chunk) {
    // zero d_out (grid-stride)
    for (int i = blockIdx.x * blockDim.x + threadIdx.x; i < n4;
         i += gridDim.x * blockDim.x)
        out[i] = make_float4(0.f, 0.f, 0.f, 0.f);

    // W[r] is [k][n] row-major fp32 -> g_Bh[r][n][k] fp16
    if (blockIdx.x < 16) {
        int r = blockIdx.x;
        for (int idx = threadIdx.x; idx < 4096; idx += blockDim.x) {
            int n = idx >> 6, k = idx & 63;
            g_Bh[r * 4096 + idx] =
                __half_as_ushort(__float2half_rn(W[r * 4096 + k * 64 + n]));
        }
    }

    // histogram
    __shared__ int cnt[16];
    if (threadIdx.x < 16) cnt[threadIdx.x] = 0;
    __syncthreads();
    int lo = blockIdx.x * chunk, hi = min(E, lo + chunk);
    for (int e = lo + threadIdx.x; e < hi; e += blockDim.x)
        atomicAdd(&cnt[et[e]], 1);
    __syncthreads();
    if (threadIdx.x < 16)
        g_blockcounts[blockIdx.x * 16 + threadIdx.x] = cnt[threadIdx.x];
}

// ---------------------------------------------------------------------------
// single block, 512 threads. warp w owns column w; lane l owns a 32-block
// chunk (register-resident -> no serial LDG chain).
__global__ void k_scan(void) {
    __shared__ int rel_total[16];
    __shared__ int relofs_s[17];
    __shared__ int tileofs_s[17];
    int w = threadIdx.x >> 5, lane = threadIdx.x & 31;

    int vals[32];
    #pragma unroll
    for (int i = 0; i < 32; i++)
        vals[i] = g_blockcounts[(lane * 32 + i) * 16 + w];

    int lane_sum = 0;
    #pragma unroll
    for (int i = 0; i < 32; i++) lane_sum += vals[i];

    // exclusive warp scan of lane sums
    int inc = lane_sum;
    #pragma unroll
    for (int d = 1; d < 32; d <<= 1) {
        int t = __shfl_up_sync(0xffffffffu, inc, d);
        if (lane >= d) inc += t;
    }
    int run = inc - lane_sum;   // exclusive base for this lane's chunk

    #pragma unroll
    for (int i = 0; i < 32; i++) {
        int v = vals[i];
        g_blockcounts[(lane * 32 + i) * 16 + w] = run;
        run += v;
    }
    if (lane == 31) rel_total[w] = run;
    __syncthreads();

    if (threadIdx.x == 0) {
        int acc = 0, tacc = 0;
        for (int r = 0; r < 16; r++) {
            relofs_s[r] = acc; tileofs_s[r] = tacc; g_relofs[r] = acc;
            acc  += rel_total[r];
            tacc += (rel_total[r] + TILE - 1) / TILE;
        }
        relofs_s[16] = acc; tileofs_s[16] = tacc; g_relofs[16] = acc;
    }
    __syncthreads();

    int ntiles = tileofs_s[16];
    for (int t = threadIdx.x; t < MAXT; t += blockDim.x) {
        if (t < ntiles) {
            int r = 0;
            while (t >= tileofs_s[r + 1]) r++;
            g_tile_rel[t]  = r;
            g_tile_base[t] = relofs_s[r] + (t - tileofs_s[r]) * TILE;
        } else {
            g_tile_rel[t] = -1;
        }
    }
}

// ---------------------------------------------------------------------------
__global__ void k_scatter(const int* __restrict__ src, const int* __restrict__ dst,
                          const int* __restrict__ et, int E, int chunk) {
    __shared__ int cur[16];
    if (threadIdx.x < 16)
        cur[threadIdx.x] = g_relofs[threadIdx.x] +
                           g_blockcounts[blockIdx.x * 16 + threadIdx.x];
    __syncthreads();
    int lo = blockIdx.x * chunk, hi = min(E, lo + chunk);
    for (int e = lo + threadIdx.x; e < hi; e += blockDim.x) {
        int r = et[e];
        int pos = atomicAdd(&cur[r], 1);
        g_src_s[pos] = src[e];
        g_dst_s[pos] = dst[e];
    }
}

// ---------------------------------------------------------------------------
// fp16 m16n8k16 HMMA (sm_80+ portable)
#define MMA_F16(d, a, b)                                                      \
    asm volatile(                                                             \
        "mma.sync.aligned.m16n8k16.row.col.f32.f16.f16.f32 "                  \
        "{%0,%1,%2,%3}, {%4,%5,%6,%7}, {%8,%9}, {%0,%1,%2,%3};"               \
        : "+f"((d)[0]), "+f"((d)[1]), "+f"((d)[2]), "+f"((d)[3])              \
        : "r"((a)[0]), "r"((a)[1]), "r"((a)[2]), "r"((a)[3]),                 \
          "r"((b)[0]), "r"((b)[1]))

// smem (halves, padded stride 72): Ah 128x72 (18432 B) | Al 18432 B |
// Bh 64x72 (9216 B) | src 512 B | dst 512 B.  D staging (128x68 f32 =
// 34816 B) overlays Ah+Al only; Bh persists across tiles of the same rel.
#define SM_AHI  0
#define SM_ALO  18432
#define SM_BHI  36864
#define SM_SRC  46080
#define SM_DST  46592
#define SMEM_DYN 47104
#define ASTRIDE 72

__global__ __launch_bounds__(BLK, 4) void k_rgcn_mma(const float* __restrict__ feat,
                                                     float* __restrict__ out) {
    extern __shared__ char smb[];
    unsigned short* Ah = (unsigned short*)(smb + SM_AHI);
    unsigned short* Al = (unsigned short*)(smb + SM_ALO);
    unsigned short* Bh = (unsigned short*)(smb + SM_BHI);
    int* srcsh = (int*)(smb + SM_SRC);
    int* dsh   = (int*)(smb + SM_DST);
    float* Dst = (float*)smb;          // epilogue staging (overlays Ah/Al)

    int tid = threadIdx.x, w = tid >> 5, lane = tid & 31;
    int g = lane >> 2, tig = lane & 3;

    const float4* featv = (const float4*)feat;

    // contiguous tile range per CTA -> B reload only on relation change
    int per = (MAXT + GRID_MMA - 1) / GRID_MMA;
    int t0 = blockIdx.x * per, t1 = min(MAXT, t0 + per);
    int cur_rel = -1;

    for (int t = t0; t < t1; t++) {
        int rel = g_tile_rel[t];
        if (rel < 0) break;
        int base = g_tile_base[t];
        int n = min(TILE, g_relofs[rel + 1] - base);

        // stage indices
        {
            int ok = tid < n;
            srcsh[tid] = ok ? g_src_s[base + tid] : -1;
            dsh[tid]   = ok ? g_dst_s[base + tid] : -1;
        }
        // copy B (8 KB = 512 uint4 chunks) only when relation changes
        if (rel != cur_rel) {
            cur_rel = rel;
            #pragma unroll
            for (int c = 0; c < 4; c++) {           // FIX: was c < 2 (half of B!)
                int p8  = tid + c * BLK;            // 512 uint4 chunks
                int idx = p8 * 8;
                int nr = idx >> 6, k = idx & 63;
                *(uint4*)(Bh + nr * ASTRIDE + k) =
                    *(const uint4*)(g_Bh + rel * 4096 + idx);
            }
        }
        __syncthreads();

        // gather + fp16 hi/lo split: 16 lanes per 256B feat row
        #pragma unroll
        for (int it = 0; it < 16; it++) {
            int p = tid + it * BLK;
            int row = p >> 4, f = p & 15;
            int s = srcsh[row];
            float4 v = (s >= 0) ? featv[(long long)s * 16 + f]
                                : make_float4(0.f, 0.f, 0.f, 0.f);
            __half hx = __float2half_rn(v.x), hy = __float2half_rn(v.y);
            __half hz = __float2half_rn(v.z), hw = __float2half_rn(v.w);
            __half lx = __float2half_rn(v.x - __half2float(hx));
            __half ly = __float2half_rn(v.y - __half2float(hy));
            __half lz = __float2half_rn(v.z - __half2float(hz));
            __half lw = __float2half_rn(v.w - __half2float(hw));
            unsigned h01 = (unsigned)__half_as_ushort(hx) |
                           ((unsigned)__half_as_ushort(hy) << 16);
            unsigned h23 = (unsigned)__half_as_ushort(hz) |
                           ((unsigned)__half_as_ushort(hw) << 16);
            unsigned l01 = (unsigned)__half_as_ushort(lx) |
                           ((unsigned)__half_as_ushort(ly) << 16);
            unsigned l23 = (unsigned)__half_as_ushort(lz) |
                           ((unsigned)__half_as_ushort(lw) << 16);
            *(uint2*)(Ah + row * ASTRIDE + f * 4) = make_uint2(h01, h23);
            *(uint2*)(Al + row * ASTRIDE + f * 4) = make_uint2(l01, l23);
        }
        __syncthreads();

        // GEMM: warp w owns rows [32w, 32w+32) = 2 m16 x 8 n8 blocks, 2 passes
        float acc[2][8][4];
        #pragma unroll
        for (int m = 0; m < 2; m++)
            #pragma unroll
            for (int nb = 0; nb < 8; nb++)
                #pragma unroll
                for (int j = 0; j < 4; j++) acc[m][nb][j] = 0.f;

        #pragma unroll
        for (int ks = 0; ks < 4; ks++) {
            int kc = ks * 16 + 2 * tig;
            unsigned ah[2][4], al[2][4];
            #pragma unroll
            for (int m = 0; m < 2; m++) {
                int r0 = (32 * w + 16 * m + g) * ASTRIDE + kc;
                int r1 = r0 + 8 * ASTRIDE;
                ah[m][0] = *(const unsigned*)(Ah + r0);
                ah[m][1] = *(const unsigned*)(Ah + r1);
                ah[m][2] = *(const unsigned*)(Ah + r0 + 8);
                ah[m][3] = *(const unsigned*)(Ah + r1 + 8);
                al[m][0] = *(const unsigned*)(Al + r0);
                al[m][1] = *(const unsigned*)(Al + r1);
                al[m][2] = *(const unsigned*)(Al + r0 + 8);
                al[m][3] = *(const unsigned*)(Al + r1 + 8);
            }
            #pragma unroll
            for (int nb = 0; nb < 8; nb++) {
                int b0 = (8 * nb + g) * ASTRIDE + kc;
                unsigned bh[2];
                bh[0] = *(const unsigned*)(Bh + b0);
                bh[1] = *(const unsigned*)(Bh + b0 + 8);
                #pragma unroll
                for (int m = 0; m < 2; m++) {
                    MMA_F16(acc[m][nb], ah[m], bh);
                    MMA_F16(acc[m][nb], al[m], bh);
                }
            }
        }
        __syncthreads();   // done reading A smem; reuse as D staging

        #pragma unroll
        for (int m = 0; m < 2; m++) {
            int r0 = 32 * w + 16 * m + g;
            #pragma unroll
            for (int nb = 0; nb < 8; nb++) {
                int c = 8 * nb + 2 * tig;
                *(float2*)(Dst + r0 * 68 + c) =
                    make_float2(acc[m][nb][0], acc[m][nb][1]);
                *(float2*)(Dst + (r0 + 8) * 68 + c) =
                    make_float2(acc[m][nb][2], acc[m][nb][3]);
            }
        }
        __syncthreads();

        // scatter: thread tid handles row tid, 16 x red.v4
        if (tid < n) {
            float* op = out + (long long)dsh[tid] * 64;
            const float4* dr = (const float4*)(Dst + tid * 68);
            #pragma unroll
            for (int q = 0; q < 16; q++) {
                float4 v = dr[q];
                asm volatile("red.global.add.v4.f32 [%0], {%1, %2, %3, %4};"
                             :: "l"(op + q * 4),
                                "f"(v.x), "f"(v.y), "f"(v.z), "f"(v.w)
                             : "memory");
            }
        }
        __syncthreads();   // staging reused as A next iteration
    }
}

// ---------------------------------------------------------------------------
extern "C" void kernel_launch(void* const* d_in, const int* in_sizes, int n_in,
                              void* d_out, int out_size) {
    const float* feat   = (const float*)d_in[0];   // [N, 64]
    const float* weight = (const float*)d_in[1];   // [16, 64, 64]
    const int*   src    = (const int*)d_in[2];     // [E]
    const int*   dst    = (const int*)d_in[3];     // [E]
    const int*   etyp   = (const int*)d_in[4];     // [E]
    float*       out    = (float*)d_out;           // [N, 64]

    int E = in_sizes[2];
    int n4 = out_size >> 2;
    int chunk = (E + NB_SORT - 1) / NB_SORT;

    cudaFuncSetAttribute(k_rgcn_mma, cudaFuncAttributeMaxDynamicSharedMemorySize,
                         SMEM_DYN);

    k_prep<<<NB_SORT, 256>>>((float4*)out, n4, weight, etyp, E, chunk);
    k_scan<<<1, 512>>>();
    k_scatter<<<NB_SORT, 256>>>(src, dst, etyp, E, chunk);
    k_rgcn_mma<<<GRID_MMA, BLK, SMEM_DYN>>>(feat, out);
}